// round 11
// baseline (speedup 1.0000x reference)
#include <cuda_runtime.h>
#include <math.h>

// Problem constants (fixed by the reference)
#define BB 256
#define TT 200
#define QQ 1000
#define TM1 199    // T - 1
#define NTHR 64    // TWO independent warps per CTA, one student each
#define NCTA (BB / 2)   // 128 CTAs -> one per SM
#define KPT 7      // steps per lane (stride 32): 32*7 = 224 >= 199

// Per-lane fixed point for the intra-warp REDUX: scale 2^18.
// Warp-total worst case ~5200 * 2^18 ≈ 1.4e9 < 2^31 (no overflow);
// quantization ≤ 32*0.5*2^-18 ≈ 6e-5 abs — far below the 1e-3 gate.
#define LSCALE 262144.0f                 // 2^18
#define INV_LSCALE_TM1 (1.0 / (262144.0 * 199.0))

// Global fixed-point: per-student loss (< 8.0) scaled by 2^40; 256 of them < 2^51.
// Completion count lives at bit 54: one atomicAdd carries payload + ticket.
#define FXSCALE 1099511627776.0          // 2^40
#define CNT_ONE (1ull << 54)
#define SUM_MASK ((1ull << 54) - 1ull)

__device__ unsigned long long g_acc = 0ull;   // packed {count[63:54], fxsum[53:0]}

__global__ void __launch_bounds__(NTHR)
fused_kernel(const float* __restrict__ logit_c,
             const float* __restrict__ logit_t,
             const int*   __restrict__ q_idx,
             const int*   __restrict__ correct,
             float*       __restrict__ out)
{
    __shared__ float sh_e[2][TM1 + 1];    // fallback only
    __shared__ float sh_pc[2][TM1 + 1];   // fallback only

    const int warp = threadIdx.x >> 5;            // 0/1 -> which student
    const int i    = threadIdx.x & 31;            // lane
    const int s    = blockIdx.x * 2 + warp;       // student id

    float* __restrict__ p_mean = out + 1;
    float* __restrict__ gt     = out + 1 + (size_t)BB * TM1;

    // ---- Pass 1: batched index/label loads (coalesced, stride 32) ----
    int   qv[KPT];
    float av[KPT];
    bool  actv[KPT];
    #pragma unroll
    for (int k = 0; k < KPT; k++) {
        const int idx = i + k * 32;
        actv[k] = (idx < TM1);
        const int base = s * TT + idx + 1;
        qv[k] = actv[k] ? __ldg(&q_idx[base])          : 0;
        av[k] = actv[k] ? (float)__ldg(&correct[base]) : 0.0f;
    }

    // ---- Pass 2: batched divergent gathers, evict-first (touched once) ----
    float xcv[KPT], xtv[KPT];
    #pragma unroll
    for (int k = 0; k < KPT; k++) {
        if (actv[k]) {
            const int idx = i + k * 32;
            const size_t row = (size_t)(s * TT + idx) * QQ + qv[k];
            xcv[k] = __ldcs(&logit_c[row]);
            xtv[k] = __ldcs(&logit_t[row]);
        } else { xcv[k] = 0.0f; xtv[k] = 0.0f; }
    }

    // ---- Pass 3: compute + elementwise streaming outputs ----
    float ev[KPT], pcv[KPT];
    float e_acc = 0.0f;
    bool  allpos = true;
    #pragma unroll
    for (int k = 0; k < KPT; k++) {
        if (actv[k]) {
            const float ec = __expf(-xcv[k]);
            const float et = __expf(-xtv[k]);
            const float pc = __fdividef(1.0f, 1.0f + ec);
            const float pt = __fdividef(1.0f, 1.0f + et);
            const int idx = i + k * 32;
            const size_t o = (size_t)s * TM1 + idx;
            __stcs(&p_mean[o], 0.5f * (pt + pc));
            __stcs(&gt[o],     av[k]);
            // BCE(sigmoid(x),a) = (1-a)*x + log1p(e^{-x}); both terms in one log
            const float e = (1.0f - av[k]) * (xcv[k] + xtv[k])
                          + __logf((1.0f + ec) * (1.0f + et));
            ev[k] = e; pcv[k] = pc;
            e_acc += e;
            allpos = allpos && (pc > 0.0f);
        } else { ev[k] = 0.0f; pcv[k] = 1.0f; }
    }

    const int wall = __all_sync(0xFFFFFFFFu, allpos);

    if (wall) {
        // Fast path: full mask, count = 199.
        // Single-op HW warp reduction in 2^18 fixed point (exact int sum).
        const int fxl = __float2int_rn(e_acc * LSCALE);
        const int rsum = __reduce_add_sync(0xFFFFFFFFu, fxl);
        if (i == 0) {
            const double loss = (double)rsum * INV_LSCALE_TM1;
            const unsigned long long fx =
                __double2ull_rn(loss * FXSCALE) + CNT_ONE;
            const unsigned long long now = atomicAdd(&g_acc, fx) + fx;
            if ((now >> 54) == (unsigned long long)BB) {
                out[0] = (float)((double)(now & SUM_MASK) * (1.0 / FXSCALE));
                g_acc  = 0ull;              // reset for next graph replay
            }
        }
    } else {
        // Rare exact dynamic-trim fallback (warp-scope sync only)
        #pragma unroll
        for (int k = 0; k < KPT; k++) {
            const int idx = i + k * 32;
            if (actv[k]) { sh_e[warp][idx] = ev[k]; sh_pc[warp][idx] = pcv[k]; }
        }
        __syncwarp();
        if (i == 0) {
            int last = -1;
            for (int j = 0; j < TM1; j++)
                if (sh_pc[warp][j] > 0.0f) last = j;
            if (last < 0) last = TM1 - 1;   // argmax-of-all-false convention
            float sum = 0.0f;
            for (int j = 0; j <= last; j++) sum += sh_e[warp][j];
            const double loss = (double)sum / (double)(last + 1);
            const unsigned long long fx =
                __double2ull_rn(loss * FXSCALE) + CNT_ONE;
            const unsigned long long now = atomicAdd(&g_acc, fx) + fx;
            if ((now >> 54) == (unsigned long long)BB) {
                out[0] = (float)((double)(now & SUM_MASK) * (1.0 / FXSCALE));
                g_acc  = 0ull;
            }
        }
    }
}

extern "C" void kernel_launch(void* const* d_in, const int* in_sizes, int n_in,
                              void* d_out, int out_size)
{
    const float* logit_c = (const float*)d_in[0];
    const float* logit_t = (const float*)d_in[1];
    const int*   q_idx   = (const int*)d_in[2];
    const int*   correct = (const int*)d_in[3];
    float* out = (float*)d_out;

    fused_kernel<<<NCTA, NTHR>>>(logit_c, logit_t, q_idx, correct, out);
}